// round 2
// baseline (speedup 1.0000x reference)
#include <cuda_runtime.h>
#include <cstdint>

// DescriptorLoss:
//   dotprod[b,p,q] = sum_d D0[b,d,p] * D1[b,d,q]      (p,q in [0,4096), d in [0,128))
//   loss = mean( mask ? max(0, 1-dot)*250 : max(0, dot-0.2) )
//
// descriptors: [B=2, D=128, HW=4096] fp32, K(=d)-major with row stride 4096.
// mask: [B, 4096, 4096] — harness delivers jnp.bool_ as int32 (0/1).

#define HW    4096
#define DDIM  128
#define NB    2
#define BM    128
#define BN    128
#define BK    16
#define NTILE (HW / BM)            // 32
#define NPART (NB * NTILE * NTILE) // 2048

__device__ float g_partials[NPART];

__global__ __launch_bounds__(256, 2)
void desc_loss_gemm_kernel(const float* __restrict__ d0,
                           const float* __restrict__ d1,
                           const int* __restrict__ mask)
{
    __shared__ float As[BK][BM];
    __shared__ float Bs[BK][BN];

    const int b  = blockIdx.z;
    const int p0 = blockIdx.y * BM;
    const int q0 = blockIdx.x * BN;

    const float* A  = d0 + (size_t)b * DDIM * HW;
    const float* Bm = d1 + (size_t)b * DDIM * HW;

    const int tid = threadIdx.x;
    const int tx  = tid & 15;   // q micro-tile
    const int ty  = tid >> 4;   // p micro-tile

    float acc[8][8];
    #pragma unroll
    for (int i = 0; i < 8; i++)
        #pragma unroll
        for (int j = 0; j < 8; j++)
            acc[i][j] = 0.0f;

    float ar[8], br[8];

    for (int k0 = 0; k0 < DDIM; k0 += BK) {
        // 16 rows x 128 floats for each of A,B: 512 float4, 256 threads -> 2 each.
        #pragma unroll
        for (int s = 0; s < 2; s++) {
            int id = tid + 256 * s;
            int kr = id >> 5;    // 0..15
            int c4 = id & 31;    // float4 column
            float4 va = *(const float4*)(A  + (size_t)(k0 + kr) * HW + p0 + c4 * 4);
            float4 vb = *(const float4*)(Bm + (size_t)(k0 + kr) * HW + q0 + c4 * 4);
            *(float4*)&As[kr][c4 * 4] = va;
            *(float4*)&Bs[kr][c4 * 4] = vb;
        }
        __syncthreads();

        #pragma unroll
        for (int k = 0; k < BK; k++) {
            #pragma unroll
            for (int i = 0; i < 8; i++) ar[i] = As[k][ty * 8 + i];
            #pragma unroll
            for (int j = 0; j < 8; j++) br[j] = Bs[k][tx * 8 + j];
            #pragma unroll
            for (int i = 0; i < 8; i++)
                #pragma unroll
                for (int j = 0; j < 8; j++)
                    acc[i][j] = fmaf(ar[i], br[j], acc[i][j]);
        }
        __syncthreads();
    }

    // Fused loss epilogue. mask is int32: 8 consecutive ints = two int4 loads
    // (q0 + tx*8 is a multiple of 8 ints -> 32B aligned).
    const int* mbase = mask + (size_t)b * HW * HW;
    float lsum = 0.0f;
    #pragma unroll
    for (int i = 0; i < 8; i++) {
        const int p = p0 + ty * 8 + i;
        const int* mp = mbase + (size_t)p * HW + q0 + tx * 8;
        int4 m0 = *(const int4*)(mp);
        int4 m1 = *(const int4*)(mp + 4);
        int mv[8] = {m0.x, m0.y, m0.z, m0.w, m1.x, m1.y, m1.z, m1.w};
        #pragma unroll
        for (int j = 0; j < 8; j++) {
            float d   = acc[i][j];
            float pos = fmaxf(0.0f, 1.0f - d) * 250.0f;
            float neg = fmaxf(0.0f, d - 0.2f);
            lsum += mv[j] ? pos : neg;
        }
    }

    // Deterministic block reduction (fixed tree order).
    __shared__ float red[256];
    red[tid] = lsum;
    __syncthreads();
    #pragma unroll
    for (int s = 128; s > 0; s >>= 1) {
        if (tid < s) red[tid] += red[tid + s];
        __syncthreads();
    }
    if (tid == 0)
        g_partials[b * (NTILE * NTILE) + blockIdx.y * NTILE + blockIdx.x] = red[0];
}

__global__ void desc_loss_reduce_kernel(float* __restrict__ out)
{
    __shared__ float red[256];
    float s = 0.0f;
    for (int i = threadIdx.x; i < NPART; i += 256)
        s += g_partials[i];
    red[threadIdx.x] = s;
    __syncthreads();
    #pragma unroll
    for (int st = 128; st > 0; st >>= 1) {
        if (threadIdx.x < st) red[threadIdx.x] += red[threadIdx.x + st];
        __syncthreads();
    }
    if (threadIdx.x == 0)
        out[0] = red[0] * (1.0f / ((float)NB * (float)HW * (float)HW));
}

extern "C" void kernel_launch(void* const* d_in, const int* in_sizes, int n_in,
                              void* d_out, int out_size)
{
    const float* d0   = (const float*)d_in[0];
    const float* d1   = (const float*)d_in[1];
    const int*   mask = (const int*)d_in[2];
    float*       out  = (float*)d_out;

    dim3 grid(NTILE, NTILE, NB);   // 32 x 32 x 2 = 2048 blocks
    desc_loss_gemm_kernel<<<grid, 256>>>(d0, d1, mask);
    desc_loss_reduce_kernel<<<1, 256>>>(out);
}

// round 4
// speedup vs baseline: 1.1007x; 1.1007x over previous
#include <cuda_runtime.h>
#include <cuda_bf16.h>
#include <cstdint>

// DescriptorLoss via mma.sync (HMMA) bf16 split-GEMM:
//   dot[b,p,q] = sum_d D0[b,d,p]*D1[b,d,q]
//   loss = mean(mask ? relu(1-dot)*250 : relu(dot-0.2))
// fp32 x -> hi=bf16(x), lo=bf16(x-hi). dot ~= Ah.Bh + Al.Bh + Ah.Bl (3 passes).
// CTA tile 64(p) x 128(q), 8 warps (2x4), warp tile 32x32, occ 2.

#define HW    4096
#define DDIM  128
#define NB    2
#define BM    64
#define BN    128
#define NPT   (HW / BM)       // 64 p-tiles
#define NQT   (HW / BN)       // 32 q-tiles
#define NPART (NB * NPT * NQT)

#define LDK   136             // padded row length (bf16 elems): 128 + 8

// smem byte offsets
#define SM_AH  0
#define SM_AL  (SM_AH + BM * LDK * 2)         // 17408
#define SM_BH  (SM_AL + BM * LDK * 2)         // 34816
#define SM_BL  (SM_BH + BN * LDK * 2)         // 69632
#define SM_RED (SM_BL + BN * LDK * 2)         // 104448
#define SM_TOT (SM_RED + 256 * 4)             // 105472

__device__ float g_partials[NPART];

__device__ __forceinline__ uint32_t bf2_pack(float x, float y) {
    __nv_bfloat162 v(__float2bfloat16(x), __float2bfloat16(y));
    return *(uint32_t*)&v;
}

__global__ __launch_bounds__(256, 2)
void desc_loss_hmma_kernel(const float* __restrict__ d0,
                           const float* __restrict__ d1,
                           const int* __restrict__ mask)
{
    extern __shared__ char smem[];
    __nv_bfloat16* Ah = (__nv_bfloat16*)(smem + SM_AH);
    __nv_bfloat16* Al = (__nv_bfloat16*)(smem + SM_AL);
    __nv_bfloat16* Bh = (__nv_bfloat16*)(smem + SM_BH);
    __nv_bfloat16* Bl = (__nv_bfloat16*)(smem + SM_BL);
    float*         red = (float*)(smem + SM_RED);

    const int tid = threadIdx.x;
    const int wid = tid >> 5;
    const int lid = tid & 31;
    const int g   = lid >> 2;      // group 0..7
    const int t   = lid & 3;       // thread-in-group

    const int b  = blockIdx.z;
    const int p0 = blockIdx.y * BM;
    const int q0 = blockIdx.x * BN;

    // ---- prologue: fp32 -> bf16 hi/lo into [row][k] smem tiles ----
    {
        const float* srcA = d0 + (size_t)b * DDIM * HW + p0;
        const float* srcB = d1 + (size_t)b * DDIM * HW + q0;
        // A: 64 d-pairs x 64 m = 4096 items
        #pragma unroll
        for (int it = 0; it < 16; it++) {
            int i  = it * 256 + tid;
            int m  = i & 63;
            int dp = i >> 6;          // 0..63
            float a0 = srcA[(size_t)(2 * dp) * HW + m];
            float a1 = srcA[(size_t)(2 * dp + 1) * HW + m];
            float h0 = __bfloat162float(__float2bfloat16(a0));
            float h1 = __bfloat162float(__float2bfloat16(a1));
            *(uint32_t*)&Ah[m * LDK + 2 * dp] = bf2_pack(a0, a1);
            *(uint32_t*)&Al[m * LDK + 2 * dp] = bf2_pack(a0 - h0, a1 - h1);
        }
        // B: 64 d-pairs x 128 n = 8192 items
        #pragma unroll
        for (int it = 0; it < 32; it++) {
            int i  = it * 256 + tid;
            int n  = i & 127;
            int dp = i >> 7;          // 0..63
            float b0 = srcB[(size_t)(2 * dp) * HW + n];
            float b1 = srcB[(size_t)(2 * dp + 1) * HW + n];
            float h0 = __bfloat162float(__float2bfloat16(b0));
            float h1 = __bfloat162float(__float2bfloat16(b1));
            *(uint32_t*)&Bh[n * LDK + 2 * dp] = bf2_pack(b0, b1);
            *(uint32_t*)&Bl[n * LDK + 2 * dp] = bf2_pack(b0 - h0, b1 - h1);
        }
    }
    __syncthreads();

    // ---- mma loop: 3 passes (Ah.Bh, Al.Bh, Ah.Bl), 8 k16-steps each ----
    const int wm = wid >> 2;       // 0..1
    const int wn = wid & 3;        // 0..3

    float acc[2][4][4];            // [m-tile][n-tile][frag]
    #pragma unroll
    for (int i = 0; i < 2; i++)
        #pragma unroll
        for (int j = 0; j < 4; j++)
            #pragma unroll
            for (int u = 0; u < 4; u++)
                acc[i][j][u] = 0.0f;

    const __nv_bfloat16* Abufs[3] = {Ah, Al, Ah};
    const __nv_bfloat16* Bbufs[3] = {Bh, Bh, Bl};

    #pragma unroll
    for (int pass = 0; pass < 3; pass++) {
        const __nv_bfloat16* A = Abufs[pass];
        const __nv_bfloat16* B = Bbufs[pass];
        #pragma unroll
        for (int s = 0; s < 8; s++) {
            const int k0 = s * 16;
            uint32_t af[2][4], bf[4][2];
            #pragma unroll
            for (int ti = 0; ti < 2; ti++) {
                const int r0 = wm * 32 + ti * 16;
                af[ti][0] = *(const uint32_t*)&A[(r0 + g) * LDK + k0 + 2 * t];
                af[ti][1] = *(const uint32_t*)&A[(r0 + g + 8) * LDK + k0 + 2 * t];
                af[ti][2] = *(const uint32_t*)&A[(r0 + g) * LDK + k0 + 2 * t + 8];
                af[ti][3] = *(const uint32_t*)&A[(r0 + g + 8) * LDK + k0 + 2 * t + 8];
            }
            #pragma unroll
            for (int tj = 0; tj < 4; tj++) {
                const int n0 = wn * 32 + tj * 8;
                bf[tj][0] = *(const uint32_t*)&B[(n0 + g) * LDK + k0 + 2 * t];
                bf[tj][1] = *(const uint32_t*)&B[(n0 + g) * LDK + k0 + 2 * t + 8];
            }
            #pragma unroll
            for (int ti = 0; ti < 2; ti++)
                #pragma unroll
                for (int tj = 0; tj < 4; tj++) {
                    asm volatile(
                        "mma.sync.aligned.m16n8k16.row.col.f32.bf16.bf16.f32 "
                        "{%0,%1,%2,%3}, {%4,%5,%6,%7}, {%8,%9}, {%0,%1,%2,%3};"
                        : "+f"(acc[ti][tj][0]), "+f"(acc[ti][tj][1]),
                          "+f"(acc[ti][tj][2]), "+f"(acc[ti][tj][3])
                        : "r"(af[ti][0]), "r"(af[ti][1]), "r"(af[ti][2]), "r"(af[ti][3]),
                          "r"(bf[tj][0]), "r"(bf[tj][1]));
                }
        }
    }

    // ---- epilogue: fuse hinge loss with mask ----
    float lsum = 0.0f;
    {
        const int* mbase = mask + (size_t)b * HW * HW + q0;
        #pragma unroll
        for (int ti = 0; ti < 2; ti++) {
            const int pr0 = p0 + wm * 32 + ti * 16 + g;
            #pragma unroll
            for (int tj = 0; tj < 4; tj++) {
                const int qc = wn * 32 + tj * 8 + 2 * t;
                int2 m0 = *(const int2*)(mbase + (size_t)pr0 * HW + qc);
                int2 m1 = *(const int2*)(mbase + (size_t)(pr0 + 8) * HW + qc);
                float dv, pos, neg;
                dv = acc[ti][tj][0];
                pos = fmaxf(0.0f, 1.0f - dv) * 250.0f; neg = fmaxf(0.0f, dv - 0.2f);
                lsum += m0.x ? pos : neg;
                dv = acc[ti][tj][1];
                pos = fmaxf(0.0f, 1.0f - dv) * 250.0f; neg = fmaxf(0.0f, dv - 0.2f);
                lsum += m0.y ? pos : neg;
                dv = acc[ti][tj][2];
                pos = fmaxf(0.0f, 1.0f - dv) * 250.0f; neg = fmaxf(0.0f, dv - 0.2f);
                lsum += m1.x ? pos : neg;
                dv = acc[ti][tj][3];
                pos = fmaxf(0.0f, 1.0f - dv) * 250.0f; neg = fmaxf(0.0f, dv - 0.2f);
                lsum += m1.y ? pos : neg;
            }
        }
    }

    // ---- deterministic block reduction ----
    red[tid] = lsum;
    __syncthreads();
    #pragma unroll
    for (int s = 128; s > 0; s >>= 1) {
        if (tid < s) red[tid] += red[tid + s];
        __syncthreads();
    }
    if (tid == 0)
        g_partials[(b * NPT + blockIdx.y) * NQT + blockIdx.x] = red[0];
}

__global__ void desc_loss_reduce_kernel(float* __restrict__ out)
{
    __shared__ float red[256];
    float s = 0.0f;
    for (int i = threadIdx.x; i < NPART; i += 256)
        s += g_partials[i];
    red[threadIdx.x] = s;
    __syncthreads();
    #pragma unroll
    for (int st = 128; st > 0; st >>= 1) {
        if (threadIdx.x < st) red[threadIdx.x] += red[threadIdx.x + st];
        __syncthreads();
    }
    if (threadIdx.x == 0)
        out[0] = red[0] * (1.0f / ((float)NB * (float)HW * (float)HW));
}

extern "C" void kernel_launch(void* const* d_in, const int* in_sizes, int n_in,
                              void* d_out, int out_size)
{
    const float* d0   = (const float*)d_in[0];
    const float* d1   = (const float*)d_in[1];
    const int*   mask = (const int*)d_in[2];
    float*       out  = (float*)d_out;

    cudaFuncSetAttribute(desc_loss_hmma_kernel,
                         cudaFuncAttributeMaxDynamicSharedMemorySize, SM_TOT);

    dim3 grid(NQT, NPT, NB);   // 32 x 64 x 2 = 4096 blocks
    desc_loss_hmma_kernel<<<grid, 256, SM_TOT>>>(d0, d1, mask);
    desc_loss_reduce_kernel<<<1, 256>>>(out);
}

// round 5
// speedup vs baseline: 3.2325x; 2.9369x over previous
#include <cuda_runtime.h>
#include <cuda_bf16.h>
#include <cstdint>

// DescriptorLoss, single-pass bf16 HMMA:
//   dot[b,p,q] = sum_d D0[b,d,p]*D1[b,d,q]
//   loss = mean(mask ? relu(1-dot)*250 : relu(dot-0.2))
// Stage 1: convert+transpose fp32 [b][d][hw] -> bf16 [b][hw][d] scratch.
// Stage 2: 128x128-tile GEMM (mma.sync m16n8k16 bf16) fused with loss.
// Stage 3: deterministic final reduce.

#define HW    4096
#define DDIM  128
#define NB    2
#define BM    128
#define BN    128
#define NQT   (HW / BN)          // 32
#define NPT   (HW / BM)          // 32
#define NPART (NB * NPT * NQT)   // 2048

#define LDK   136                // padded k-stride in bf16 elems (272 B rows)

#define SM_A   0
#define SM_B   (BM * LDK * 2)               // 34816
#define SM_RED (SM_B + BN * LDK * 2)        // 69632
#define SM_TOT (SM_RED + 512 * 4)           // 71680

__device__ __nv_bfloat16 g_d0t[(size_t)NB * HW * DDIM];  // [b][hw][d]
__device__ __nv_bfloat16 g_d1t[(size_t)NB * HW * DDIM];
__device__ float g_partials[NPART];

// ---------- stage 1: convert + transpose ----------
__global__ __launch_bounds__(256)
void conv_kernel(const float* __restrict__ d0, const float* __restrict__ d1)
{
    __shared__ float tile[32][33];
    const int which = blockIdx.z & 1;
    const int b     = blockIdx.z >> 1;
    const float* src = (which ? d1 : d0) + (size_t)b * DDIM * HW;
    __nv_bfloat16* dst = (which ? g_d1t : g_d0t) + (size_t)b * HW * DDIM;

    const int hw0 = blockIdx.x * 32;
    const int dd0 = blockIdx.y * 32;
    const int tx = threadIdx.x, ty = threadIdx.y;   // 32 x 8

    #pragma unroll
    for (int j = 0; j < 4; j++)
        tile[ty + 8 * j][tx] = src[(size_t)(dd0 + ty + 8 * j) * HW + hw0 + tx];
    __syncthreads();
    #pragma unroll
    for (int j = 0; j < 4; j++)
        dst[(size_t)(hw0 + ty + 8 * j) * DDIM + dd0 + tx] =
            __float2bfloat16(tile[tx][ty + 8 * j]);
}

// ---------- stage 2: GEMM + fused loss ----------
__global__ __launch_bounds__(512, 2)
void desc_loss_hmma_kernel(const int* __restrict__ mask)
{
    extern __shared__ char smem[];
    __nv_bfloat16* Asm = (__nv_bfloat16*)(smem + SM_A);
    __nv_bfloat16* Bsm = (__nv_bfloat16*)(smem + SM_B);
    float*         red = (float*)(smem + SM_RED);

    const int tid = threadIdx.x;
    const int wid = tid >> 5;
    const int lid = tid & 31;
    const int g   = lid >> 2;      // 0..7
    const int t   = lid & 3;       // 0..3

    const int b  = blockIdx.z;
    const int p0 = blockIdx.y * BM;
    const int q0 = blockIdx.x * BN;

    // prologue: bf16 scratch -> smem (16B copies; conflict-free STS.128)
    {
        const __nv_bfloat16* gA = g_d0t + (size_t)b * HW * DDIM + (size_t)p0 * DDIM;
        const __nv_bfloat16* gB = g_d1t + (size_t)b * HW * DDIM + (size_t)q0 * DDIM;
        #pragma unroll
        for (int it = 0; it < 4; it++) {
            int i = it * 512 + tid;
            int r = i >> 4;          // row 0..127
            int c = i & 15;          // 16B chunk
            uint4 va = *(const uint4*)(gA + (size_t)r * DDIM + c * 8);
            uint4 vb = *(const uint4*)(gB + (size_t)r * DDIM + c * 8);
            *(uint4*)((char*)Asm + r * (LDK * 2) + c * 16) = va;
            *(uint4*)((char*)Bsm + r * (LDK * 2) + c * 16) = vb;
        }
    }
    __syncthreads();

    // warp tiling: 16 warps = 4(m) x 4(n), warp tile 32x32
    const int wm = wid & 3;
    const int wn = wid >> 2;

    float acc[2][4][4];
    #pragma unroll
    for (int i = 0; i < 2; i++)
        #pragma unroll
        for (int j = 0; j < 4; j++)
            #pragma unroll
            for (int u = 0; u < 4; u++)
                acc[i][j][u] = 0.0f;

    #pragma unroll
    for (int s = 0; s < 8; s++) {
        const int k0 = s * 16;
        uint32_t af[2][4], bf[4][2];
        #pragma unroll
        for (int ti = 0; ti < 2; ti++) {
            const int r0 = wm * 32 + ti * 16;
            af[ti][0] = *(const uint32_t*)&Asm[(r0 + g) * LDK + k0 + 2 * t];
            af[ti][1] = *(const uint32_t*)&Asm[(r0 + g + 8) * LDK + k0 + 2 * t];
            af[ti][2] = *(const uint32_t*)&Asm[(r0 + g) * LDK + k0 + 2 * t + 8];
            af[ti][3] = *(const uint32_t*)&Asm[(r0 + g + 8) * LDK + k0 + 2 * t + 8];
        }
        #pragma unroll
        for (int tj = 0; tj < 4; tj++) {
            const int n0 = wn * 32 + tj * 8;
            bf[tj][0] = *(const uint32_t*)&Bsm[(n0 + g) * LDK + k0 + 2 * t];
            bf[tj][1] = *(const uint32_t*)&Bsm[(n0 + g) * LDK + k0 + 2 * t + 8];
        }
        #pragma unroll
        for (int ti = 0; ti < 2; ti++)
            #pragma unroll
            for (int tj = 0; tj < 4; tj++) {
                asm volatile(
                    "mma.sync.aligned.m16n8k16.row.col.f32.bf16.bf16.f32 "
                    "{%0,%1,%2,%3}, {%4,%5,%6,%7}, {%8,%9}, {%0,%1,%2,%3};"
                    : "+f"(acc[ti][tj][0]), "+f"(acc[ti][tj][1]),
                      "+f"(acc[ti][tj][2]), "+f"(acc[ti][tj][3])
                    : "r"(af[ti][0]), "r"(af[ti][1]), "r"(af[ti][2]), "r"(af[ti][3]),
                      "r"(bf[tj][0]), "r"(bf[tj][1]));
            }
    }

    // epilogue: fused hinge loss with mask (int32)
    float lsum = 0.0f;
    {
        const int* mbase = mask + (size_t)b * HW * HW + q0;
        #pragma unroll
        for (int ti = 0; ti < 2; ti++) {
            const int pr0 = p0 + wm * 32 + ti * 16 + g;
            #pragma unroll
            for (int tj = 0; tj < 4; tj++) {
                const int qc = wn * 32 + tj * 8 + 2 * t;
                int2 m0 = *(const int2*)(mbase + (size_t)pr0 * HW + qc);
                int2 m1 = *(const int2*)(mbase + (size_t)(pr0 + 8) * HW + qc);
                float dv, pos, neg;
                dv = acc[ti][tj][0];
                pos = fmaxf(0.0f, 1.0f - dv) * 250.0f; neg = fmaxf(0.0f, dv - 0.2f);
                lsum += m0.x ? pos : neg;
                dv = acc[ti][tj][1];
                pos = fmaxf(0.0f, 1.0f - dv) * 250.0f; neg = fmaxf(0.0f, dv - 0.2f);
                lsum += m0.y ? pos : neg;
                dv = acc[ti][tj][2];
                pos = fmaxf(0.0f, 1.0f - dv) * 250.0f; neg = fmaxf(0.0f, dv - 0.2f);
                lsum += m1.x ? pos : neg;
                dv = acc[ti][tj][3];
                pos = fmaxf(0.0f, 1.0f - dv) * 250.0f; neg = fmaxf(0.0f, dv - 0.2f);
                lsum += m1.y ? pos : neg;
            }
        }
    }

    // deterministic block reduction over 512 threads
    red[tid] = lsum;
    __syncthreads();
    #pragma unroll
    for (int s = 256; s > 0; s >>= 1) {
        if (tid < s) red[tid] += red[tid + s];
        __syncthreads();
    }
    if (tid == 0)
        g_partials[(b * NPT + blockIdx.y) * NQT + blockIdx.x] = red[0];
}

// ---------- stage 3: final reduce ----------
__global__ __launch_bounds__(512)
void desc_loss_reduce_kernel(float* __restrict__ out)
{
    __shared__ float red[512];
    const int tid = threadIdx.x;
    // 4 independent loads (MLP), fixed order
    float s = (g_partials[tid] + g_partials[tid + 512])
            + (g_partials[tid + 1024] + g_partials[tid + 1536]);
    red[tid] = s;
    __syncthreads();
    #pragma unroll
    for (int st = 256; st > 0; st >>= 1) {
        if (tid < st) red[tid] += red[tid + st];
        __syncthreads();
    }
    if (tid == 0)
        out[0] = red[0] * (1.0f / ((float)NB * (float)HW * (float)HW));
}

extern "C" void kernel_launch(void* const* d_in, const int* in_sizes, int n_in,
                              void* d_out, int out_size)
{
    const float* d0   = (const float*)d_in[0];
    const float* d1   = (const float*)d_in[1];
    const int*   mask = (const int*)d_in[2];
    float*       out  = (float*)d_out;

    cudaFuncSetAttribute(desc_loss_hmma_kernel,
                         cudaFuncAttributeMaxDynamicSharedMemorySize, SM_TOT);

    conv_kernel<<<dim3(HW / 32, DDIM / 32, 2 * NB), dim3(32, 8)>>>(d0, d1);
    desc_loss_hmma_kernel<<<dim3(NQT, NPT, NB), 512, SM_TOT>>>(mask);
    desc_loss_reduce_kernel<<<1, 512>>>(out);
}